// round 1
// baseline (speedup 1.0000x reference)
#include <cuda_runtime.h>

#define NN 100000
#define EE 800000

// ---------------- scratch (device globals: no allocation allowed) ----------
__device__ float    g_h[NN * 128];     // projected features, layer-current
__device__ float    g_out[NN * 128];   // aggregation accumulator
__device__ float    g_feat2[NN * 128]; // relu(out1 + b1) -> layer-2 input
__device__ float    g_el[NN * 4];
__device__ float    g_er[NN * 4];
__device__ float    g_s[NN * 4];       // softmax denominators
__device__ unsigned g_mk[NN * 4];      // segment-max as monotone uint keys
__device__ float    g_e[EE * 4];       // edge logits, then exp(e - m)

// monotone float <-> uint key (total order matches float order)
__device__ __forceinline__ unsigned fkey(float f) {
    unsigned u = __float_as_uint(f);
    return (u & 0x80000000u) ? ~u : (u | 0x80000000u);
}
__device__ __forceinline__ float finv(unsigned k) {
    unsigned u = (k & 0x80000000u) ? (k ^ 0x80000000u) : ~k;
    return __uint_as_float(u);
}
__device__ __forceinline__ void red_add_v4(float* a, float4 v) {
    asm volatile("red.global.add.v4.f32 [%0], {%1,%2,%3,%4};"
                 :: "l"(a), "f"(v.x), "f"(v.y), "f"(v.z), "f"(v.w) : "memory");
}
__device__ __forceinline__ float lrelu(float v) { return v > 0.f ? v : 0.2f * v; }

// ---------------- kernels --------------------------------------------------

__global__ void k_init() {
    int i = blockIdx.x * 256 + threadIdx.x;
    if (i < NN * 128) g_out[i] = 0.f;
    if (i < NN * 4) { g_mk[i] = 0u; g_s[i] = 0.f; }
}

// 64 rows/block, 256 threads. Thread (rg, cg): 8 rows x 4 cols register tile.
// Fused epilogue computes el/er via 8-lane shuffle reduction per head.
__global__ void __launch_bounds__(256) k_gemm(
    const float* __restrict__ xext, int use_internal,
    const float* __restrict__ W,
    const float* __restrict__ al, const float* __restrict__ ar)
{
    const float* x = use_internal ? g_feat2 : xext;
    __shared__ float4 Ws[32][32];   // 32 k x 128 cols (as float4)
    __shared__ float  xs[32][65];   // 32 k x 64 rows (+pad)

    int t = threadIdx.x;
    int row0 = blockIdx.x * 64;
    int rg = t >> 5;       // 0..7 -> rows rg*8 .. rg*8+7
    int cg = t & 31;       // 0..31 -> cols cg*4 .. cg*4+3

    float acc[8][4];
#pragma unroll
    for (int i = 0; i < 8; i++)
#pragma unroll
        for (int j = 0; j < 4; j++) acc[i][j] = 0.f;

    for (int k0 = 0; k0 < 128; k0 += 32) {
        __syncthreads();
        // W chunk: 32x128 floats = 1024 float4, 4 per thread (coalesced)
#pragma unroll
        for (int l = 0; l < 4; l++) {
            int idx = t + l * 256;
            int kk = idx >> 5, c4 = idx & 31;
            Ws[kk][c4] = ((const float4*)(W + (k0 + kk) * 128))[c4];
        }
        // x chunk: 64 rows x 32 k, transposed into smem (coalesced gmem reads)
#pragma unroll
        for (int l = 0; l < 8; l++) {
            int idx = t + l * 256;
            int r = idx >> 5, kk = idx & 31;
            int n = row0 + r;
            xs[kk][r] = (n < NN) ? x[n * 128 + k0 + kk] : 0.f;
        }
        __syncthreads();
#pragma unroll
        for (int kk = 0; kk < 32; kk++) {
            float4 wv = Ws[kk][cg];
#pragma unroll
            for (int i = 0; i < 8; i++) {
                float xv = xs[kk][rg * 8 + i];
                acc[i][0] += xv * wv.x; acc[i][1] += xv * wv.y;
                acc[i][2] += xv * wv.z; acc[i][3] += xv * wv.w;
            }
        }
    }

    // epilogue: write h, compute el/er (head hd = cg/8, 8 lanes per head)
    float4 alv = ((const float4*)al)[cg];
    float4 arv = ((const float4*)ar)[cg];
    int hd = cg >> 3;
#pragma unroll
    for (int i = 0; i < 8; i++) {
        int n = row0 + rg * 8 + i;
        float pel = acc[i][0]*alv.x + acc[i][1]*alv.y + acc[i][2]*alv.z + acc[i][3]*alv.w;
        float per = acc[i][0]*arv.x + acc[i][1]*arv.y + acc[i][2]*arv.z + acc[i][3]*arv.w;
#pragma unroll
        for (int off = 4; off >= 1; off >>= 1) {
            pel += __shfl_down_sync(0xffffffffu, pel, off);
            per += __shfl_down_sync(0xffffffffu, per, off);
        }
        if (n < NN) {
            ((float4*)(g_h + n * 128))[cg] =
                make_float4(acc[i][0], acc[i][1], acc[i][2], acc[i][3]);
            if ((cg & 7) == 0) { g_el[n * 4 + hd] = pel; g_er[n * 4 + hd] = per; }
        }
    }
}

// pass A: edge logits + segment max
__global__ void k_edge_a(const int* __restrict__ src, const int* __restrict__ dst) {
    int e = blockIdx.x * 256 + threadIdx.x;
    if (e >= EE) return;
    int s_ = src[e], d_ = dst[e];
    float4 l = ((const float4*)g_el)[s_];
    float4 r = ((const float4*)g_er)[d_];
    float4 ev;
    ev.x = lrelu(l.x + r.x); ev.y = lrelu(l.y + r.y);
    ev.z = lrelu(l.z + r.z); ev.w = lrelu(l.w + r.w);
    ((float4*)g_e)[e] = ev;
    atomicMax(&g_mk[d_ * 4 + 0], fkey(ev.x));
    atomicMax(&g_mk[d_ * 4 + 1], fkey(ev.y));
    atomicMax(&g_mk[d_ * 4 + 2], fkey(ev.z));
    atomicMax(&g_mk[d_ * 4 + 3], fkey(ev.w));
}

// pass B: exp(e - m) + segment sum (vector reduction)
__global__ void k_edge_b(const int* __restrict__ dst) {
    int e = blockIdx.x * 256 + threadIdx.x;
    if (e >= EE) return;
    int d_ = dst[e];
    float4 ev = ((const float4*)g_e)[e];
    uint4 mk = ((const uint4*)g_mk)[d_];
    float4 ex;
    ex.x = __expf(ev.x - finv(mk.x));
    ex.y = __expf(ev.y - finv(mk.y));
    ex.z = __expf(ev.z - finv(mk.z));
    ex.w = __expf(ev.w - finv(mk.w));
    ((float4*)g_e)[e] = ex;
    red_add_v4(&g_s[d_ * 4], ex);
}

// pass C: warp per edge, gather h[src]*a -> scatter-add out[dst] (512B each)
__global__ void k_edge_c(const int* __restrict__ src, const int* __restrict__ dst) {
    int gt = blockIdx.x * 256 + threadIdx.x;
    int e = gt >> 5;
    if (e >= EE) return;
    int lane = gt & 31;
    int s_ = src[e], d_ = dst[e];
    int hd = lane >> 3;
    float a = g_e[e * 4 + hd] / g_s[d_ * 4 + hd];
    float4 hv = ((const float4*)(g_h + s_ * 128))[lane];
    red_add_v4(g_out + d_ * 128 + lane * 4,
               make_float4(hv.x * a, hv.y * a, hv.z * a, hv.w * a));
}

__global__ void k_relu_bias(const float* __restrict__ b) {
    int i = blockIdx.x * 256 + threadIdx.x;
    if (i >= NN * 128) return;
    float v = g_out[i] + b[i & 127];
    g_feat2[i] = v > 0.f ? v : 0.f;
}

__global__ void k_final(const float* __restrict__ b, float* __restrict__ out) {
    int i = blockIdx.x * 256 + threadIdx.x;
    if (i >= NN * 32) return;
    int n = i >> 5, o = i & 31;
    float s = 0.f;
#pragma unroll
    for (int hd = 0; hd < 4; hd++)
        s += g_out[n * 128 + hd * 32 + o] + b[hd * 32 + o];
    out[i] = 0.25f * s;
}

// ---------------- launch ---------------------------------------------------
extern "C" void kernel_launch(void* const* d_in, const int* in_sizes, int n_in,
                              void* d_out, int out_size)
{
    const float* feat = (const float*)d_in[0];
    const int*   src  = (const int*)d_in[1];
    const int*   dst  = (const int*)d_in[2];
    const float* W1   = (const float*)d_in[3];
    const float* al1  = (const float*)d_in[4];
    const float* ar1  = (const float*)d_in[5];
    const float* b1   = (const float*)d_in[6];
    const float* W2   = (const float*)d_in[7];
    const float* al2  = (const float*)d_in[8];
    const float* ar2  = (const float*)d_in[9];
    const float* b2   = (const float*)d_in[10];
    float* out = (float*)d_out;

    const int G_INIT = (NN * 128 + 255) / 256;
    const int G_GEMM = (NN + 63) / 64;
    const int G_EDGE = (EE + 255) / 256;
    const int G_EDGC = (EE * 32 + 255) / 256;
    const int G_FIN  = (NN * 32 + 255) / 256;

    // ---- layer 1 ----
    k_init<<<G_INIT, 256>>>();
    k_gemm<<<G_GEMM, 256>>>(feat, 0, W1, al1, ar1);
    k_edge_a<<<G_EDGE, 256>>>(src, dst);
    k_edge_b<<<G_EDGE, 256>>>(dst);
    k_edge_c<<<G_EDGC, 256>>>(src, dst);
    k_relu_bias<<<G_INIT, 256>>>(b1);

    // ---- layer 2 ----
    k_init<<<G_INIT, 256>>>();
    k_gemm<<<G_GEMM, 256>>>(nullptr, 1, W2, al2, ar2);
    k_edge_a<<<G_EDGE, 256>>>(src, dst);
    k_edge_b<<<G_EDGE, 256>>>(dst);
    k_edge_c<<<G_EDGC, 256>>>(src, dst);
    k_final<<<G_FIN, 256>>>(b2, out);
}

// round 2
// speedup vs baseline: 1.8749x; 1.8749x over previous
#include <cuda_runtime.h>

#define NN 100000
#define EE 800000
#define NB 98            // scan blocks: ceil(100000/1024)

// ---------------- scratch (device globals) ---------------------------------
__device__ float g_h[NN * 128];      // projected features
__device__ float g_feat2[NN * 128];  // relu(out1 + b1) -> layer-2 input
__device__ float g_el[NN * 4];
__device__ float g_er[NN * 4];
__device__ float g_e[EE * 4];        // edge logits -> exp, CSR order
__device__ int   g_cnt[NN];
__device__ int   g_off[NN + 1];      // CSR row offsets (by dst)
__device__ int   g_cur[NN];          // fill cursors
__device__ int   g_esrc[EE];         // src node per CSR slot
__device__ int   g_bsum[NB];

__device__ __forceinline__ float lrelu(float v) { return v > 0.f ? v : 0.2f * v; }

// ---------------- CSR build ------------------------------------------------
__global__ void k_zero_cnt() {
    int i = blockIdx.x * 256 + threadIdx.x;
    if (i < NN) g_cnt[i] = 0;
}
__global__ void k_count(const int* __restrict__ dst) {
    int e = blockIdx.x * 256 + threadIdx.x;
    if (e < EE) atomicAdd(&g_cnt[dst[e]], 1);
}
__global__ void __launch_bounds__(1024) k_scan1() {
    __shared__ int sh[1024];
    int t = threadIdx.x, i = blockIdx.x * 1024 + t;
    int v = (i < NN) ? g_cnt[i] : 0;
    sh[t] = v; __syncthreads();
#pragma unroll
    for (int d = 1; d < 1024; d <<= 1) {
        int add = (t >= d) ? sh[t - d] : 0;
        __syncthreads();
        sh[t] += add;
        __syncthreads();
    }
    if (i < NN) g_off[i] = sh[t] - v;             // exclusive within block
    if (t == 1023) g_bsum[blockIdx.x] = sh[1023]; // block total
}
__global__ void k_scan2() {
    if (threadIdx.x == 0) {
        int run = 0;
        for (int b = 0; b < NB; b++) { int t = g_bsum[b]; g_bsum[b] = run; run += t; }
    }
}
__global__ void k_scan3() {
    int i = blockIdx.x * 256 + threadIdx.x;
    if (i < NN) {
        int o = g_off[i] + g_bsum[i >> 10];
        g_off[i] = o;
        g_cur[i] = o;
    }
    if (i == 0) g_off[NN] = EE;
}
__global__ void k_fill(const int* __restrict__ src, const int* __restrict__ dst) {
    int e = blockIdx.x * 256 + threadIdx.x;
    if (e >= EE) return;
    int p = atomicAdd(&g_cur[dst[e]], 1);
    g_esrc[p] = src[e];
}

// ---------------- projection GEMM (fused el/er epilogue) --------------------
__global__ void __launch_bounds__(256) k_gemm(
    const float* __restrict__ xext, int use_internal,
    const float* __restrict__ W,
    const float* __restrict__ al, const float* __restrict__ ar)
{
    const float* x = use_internal ? g_feat2 : xext;
    __shared__ float4 Ws[32][32];
    __shared__ float  xs[32][65];

    int t = threadIdx.x;
    int row0 = blockIdx.x * 64;
    int rg = t >> 5, cg = t & 31;

    float acc[8][4];
#pragma unroll
    for (int i = 0; i < 8; i++)
#pragma unroll
        for (int j = 0; j < 4; j++) acc[i][j] = 0.f;

    for (int k0 = 0; k0 < 128; k0 += 32) {
        __syncthreads();
#pragma unroll
        for (int l = 0; l < 4; l++) {
            int idx = t + l * 256;
            int kk = idx >> 5, c4 = idx & 31;
            Ws[kk][c4] = ((const float4*)(W + (k0 + kk) * 128))[c4];
        }
#pragma unroll
        for (int l = 0; l < 8; l++) {
            int idx = t + l * 256;
            int r = idx >> 5, kk = idx & 31;
            int n = row0 + r;
            xs[kk][r] = (n < NN) ? x[n * 128 + k0 + kk] : 0.f;
        }
        __syncthreads();
#pragma unroll
        for (int kk = 0; kk < 32; kk++) {
            float4 wv = Ws[kk][cg];
#pragma unroll
            for (int i = 0; i < 8; i++) {
                float xv = xs[kk][rg * 8 + i];
                acc[i][0] += xv * wv.x; acc[i][1] += xv * wv.y;
                acc[i][2] += xv * wv.z; acc[i][3] += xv * wv.w;
            }
        }
    }

    float4 alv = ((const float4*)al)[cg];
    float4 arv = ((const float4*)ar)[cg];
    int hd = cg >> 3;
#pragma unroll
    for (int i = 0; i < 8; i++) {
        int n = row0 + rg * 8 + i;
        float pel = acc[i][0]*alv.x + acc[i][1]*alv.y + acc[i][2]*alv.z + acc[i][3]*alv.w;
        float per = acc[i][0]*arv.x + acc[i][1]*arv.y + acc[i][2]*arv.z + acc[i][3]*arv.w;
#pragma unroll
        for (int off = 4; off >= 1; off >>= 1) {
            pel += __shfl_down_sync(0xffffffffu, pel, off);
            per += __shfl_down_sync(0xffffffffu, per, off);
        }
        if (n < NN) {
            ((float4*)(g_h + n * 128))[cg] =
                make_float4(acc[i][0], acc[i][1], acc[i][2], acc[i][3]);
            if ((cg & 7) == 0) { g_el[n * 4 + hd] = pel; g_er[n * 4 + hd] = per; }
        }
    }
}

// ---------------- fused per-node softmax + aggregation ----------------------
// warp per dst node: pass1 logits+max, pass2 exp+sum, pass3 gather-aggregate.
// layer==1: write relu(acc + b) to g_feat2. layer==2: head-mean + bias to out.
__global__ void __launch_bounds__(256) k_node(
    const float* __restrict__ b, float* __restrict__ out, int layer)
{
    int gt = blockIdx.x * 256 + threadIdx.x;
    int n = gt >> 5;
    if (n >= NN) return;
    int lane = gt & 31;

    int off = g_off[n];
    int deg = g_off[n + 1] - off;

    float4 er4 = ((const float4*)g_er)[n];

    // pass 1: edge logits + warp max
    float4 m = make_float4(-1e30f, -1e30f, -1e30f, -1e30f);
    for (int j = lane; j < deg; j += 32) {
        int s = g_esrc[off + j];
        float4 l4 = ((const float4*)g_el)[s];
        float4 e4;
        e4.x = lrelu(l4.x + er4.x); e4.y = lrelu(l4.y + er4.y);
        e4.z = lrelu(l4.z + er4.z); e4.w = lrelu(l4.w + er4.w);
        ((float4*)g_e)[off + j] = e4;
        m.x = fmaxf(m.x, e4.x); m.y = fmaxf(m.y, e4.y);
        m.z = fmaxf(m.z, e4.z); m.w = fmaxf(m.w, e4.w);
    }
#pragma unroll
    for (int o = 16; o; o >>= 1) {
        m.x = fmaxf(m.x, __shfl_xor_sync(0xffffffffu, m.x, o));
        m.y = fmaxf(m.y, __shfl_xor_sync(0xffffffffu, m.y, o));
        m.z = fmaxf(m.z, __shfl_xor_sync(0xffffffffu, m.z, o));
        m.w = fmaxf(m.w, __shfl_xor_sync(0xffffffffu, m.w, o));
    }

    // pass 2: exp + warp sum
    float4 s4 = make_float4(0.f, 0.f, 0.f, 0.f);
    for (int j = lane; j < deg; j += 32) {
        float4 e4 = ((const float4*)g_e)[off + j];
        float4 ex;
        ex.x = __expf(e4.x - m.x); ex.y = __expf(e4.y - m.y);
        ex.z = __expf(e4.z - m.z); ex.w = __expf(e4.w - m.w);
        ((float4*)g_e)[off + j] = ex;
        s4.x += ex.x; s4.y += ex.y; s4.z += ex.z; s4.w += ex.w;
    }
#pragma unroll
    for (int o = 16; o; o >>= 1) {
        s4.x += __shfl_xor_sync(0xffffffffu, s4.x, o);
        s4.y += __shfl_xor_sync(0xffffffffu, s4.y, o);
        s4.z += __shfl_xor_sync(0xffffffffu, s4.z, o);
        s4.w += __shfl_xor_sync(0xffffffffu, s4.w, o);
    }
    int hd = lane >> 3;
    float rinv = 0.f;
    if (deg > 0) {
        float sh = hd == 0 ? s4.x : hd == 1 ? s4.y : hd == 2 ? s4.z : s4.w;
        rinv = 1.f / sh;
    }

    // pass 3: gather-aggregate (serial over edges, lanes over 128 features)
    float4 acc = make_float4(0.f, 0.f, 0.f, 0.f);
    const float4* hb = (const float4*)g_h;
    const float* ge = g_e;
    for (int j = 0; j < deg; j++) {
        int s = g_esrc[off + j];
        float a = ge[(off + j) * 4 + hd] * rinv;
        float4 hv = hb[s * 32 + lane];
        acc.x += hv.x * a; acc.y += hv.y * a;
        acc.z += hv.z * a; acc.w += hv.w * a;
    }

    float4 b4 = ((const float4*)b)[lane];
    acc.x += b4.x; acc.y += b4.y; acc.z += b4.z; acc.w += b4.w;

    if (layer == 1) {
        acc.x = fmaxf(acc.x, 0.f); acc.y = fmaxf(acc.y, 0.f);
        acc.z = fmaxf(acc.z, 0.f); acc.w = fmaxf(acc.w, 0.f);
        ((float4*)(g_feat2 + n * 128))[lane] = acc;
    } else {
        // mean over heads: head = lane>>3, xor lane bits 3,4 sums heads
#pragma unroll
        for (int o = 8; o <= 16; o <<= 1) {
            acc.x += __shfl_xor_sync(0xffffffffu, acc.x, o);
            acc.y += __shfl_xor_sync(0xffffffffu, acc.y, o);
            acc.z += __shfl_xor_sync(0xffffffffu, acc.z, o);
            acc.w += __shfl_xor_sync(0xffffffffu, acc.w, o);
        }
        if (lane < 8) {
            float4 r = make_float4(acc.x * 0.25f, acc.y * 0.25f,
                                   acc.z * 0.25f, acc.w * 0.25f);
            ((float4*)(out + n * 32))[lane] = r;
        }
    }
}

// ---------------- launch ---------------------------------------------------
extern "C" void kernel_launch(void* const* d_in, const int* in_sizes, int n_in,
                              void* d_out, int out_size)
{
    const float* feat = (const float*)d_in[0];
    const int*   src  = (const int*)d_in[1];
    const int*   dst  = (const int*)d_in[2];
    const float* W1   = (const float*)d_in[3];
    const float* al1  = (const float*)d_in[4];
    const float* ar1  = (const float*)d_in[5];
    const float* b1   = (const float*)d_in[6];
    const float* W2   = (const float*)d_in[7];
    const float* al2  = (const float*)d_in[8];
    const float* ar2  = (const float*)d_in[9];
    const float* b2   = (const float*)d_in[10];
    float* out = (float*)d_out;

    const int G_N    = (NN + 255) / 256;
    const int G_E    = (EE + 255) / 256;
    const int G_GEMM = (NN + 63) / 64;
    const int G_NODE = (NN * 32 + 255) / 256;

    // ---- CSR build (shared by both layers) ----
    k_zero_cnt<<<G_N, 256>>>();
    k_count<<<G_E, 256>>>(dst);
    k_scan1<<<NB, 1024>>>();
    k_scan2<<<1, 32>>>();
    k_scan3<<<G_N, 256>>>();
    k_fill<<<G_E, 256>>>(src, dst);

    // ---- layer 1 ----
    k_gemm<<<G_GEMM, 256>>>(feat, 0, W1, al1, ar1);
    k_node<<<G_NODE, 256>>>(b1, nullptr, 1);

    // ---- layer 2 ----
    k_gemm<<<G_GEMM, 256>>>(nullptr, 1, W2, al2, ar2);
    k_node<<<G_NODE, 256>>>(b2, out, 2);
}

// round 4
// speedup vs baseline: 2.0375x; 1.0867x over previous
#include <cuda_runtime.h>

#define NN 100000
#define EE 800000
#define NB 98            // scan blocks: ceil(100000/1024)

// ---------------- scratch (device globals) ---------------------------------
__device__ float    g_h[NN * 128];      // projected features
__device__ float    g_feat2[NN * 128];  // relu(out1 + b1) -> layer-2 input
__device__ float    g_el[NN * 4];
__device__ float    g_er[NN * 4];
__device__ float    g_e[EE * 4];        // edge logits -> exp, CSR order
__device__ int      g_cnt[NN];
__device__ int      g_off[NN + 1];      // CSR row offsets (by dst)
__device__ int      g_cur[NN];          // fill cursors
__device__ int      g_esrc[EE];         // src node per CSR slot
__device__ int      g_bsum[NB];
__device__ unsigned g_Whi[2][128 * 128];  // tf32 hi parts of W1, W2
__device__ unsigned g_Wlo[2][128 * 128];  // tf32 lo parts

__device__ __forceinline__ float lrelu(float v) { return v > 0.f ? v : 0.2f * v; }

__device__ __forceinline__ unsigned to_tf32(float f) {
    unsigned u;
    asm("cvt.rna.tf32.f32 %0, %1;" : "=r"(u) : "f"(f));
    return u;
}

#define MMA_TF32(c, a0, a1, a2, a3, b0, b1)                                    \
    asm volatile(                                                              \
        "mma.sync.aligned.m16n8k8.row.col.f32.tf32.tf32.f32 "                  \
        "{%0,%1,%2,%3}, {%4,%5,%6,%7}, {%8,%9}, {%0,%1,%2,%3};"                \
        : "+f"(c[0]), "+f"(c[1]), "+f"(c[2]), "+f"(c[3])                       \
        : "r"(a0), "r"(a1), "r"(a2), "r"(a3), "r"(b0), "r"(b1))

// ---------------- CSR build ------------------------------------------------
__global__ void k_zero_cnt() {
    int i = blockIdx.x * 256 + threadIdx.x;
    if (i < NN) g_cnt[i] = 0;
}
__global__ void k_count(const int* __restrict__ dst) {
    int e = blockIdx.x * 256 + threadIdx.x;
    if (e < EE) atomicAdd(&g_cnt[dst[e]], 1);
}
__global__ void __launch_bounds__(1024) k_scan1() {
    __shared__ int sh[1024];
    int t = threadIdx.x, i = blockIdx.x * 1024 + t;
    int v = (i < NN) ? g_cnt[i] : 0;
    sh[t] = v; __syncthreads();
#pragma unroll
    for (int d = 1; d < 1024; d <<= 1) {
        int add = (t >= d) ? sh[t - d] : 0;
        __syncthreads();
        sh[t] += add;
        __syncthreads();
    }
    if (i < NN) g_off[i] = sh[t] - v;
    if (t == 1023) g_bsum[blockIdx.x] = sh[1023];
}
__global__ void __launch_bounds__(128) k_scan2() {
    __shared__ int sh[128];
    int t = threadIdx.x;
    int v = (t < NB) ? g_bsum[t] : 0;
    sh[t] = v; __syncthreads();
#pragma unroll
    for (int d = 1; d < 128; d <<= 1) {
        int add = (t >= d) ? sh[t - d] : 0;
        __syncthreads();
        sh[t] += add;
        __syncthreads();
    }
    if (t < NB) g_bsum[t] = sh[t] - v;   // exclusive
}
__global__ void k_scan3() {
    int i = blockIdx.x * 256 + threadIdx.x;
    if (i < NN) {
        int o = g_off[i] + g_bsum[i >> 10];
        g_off[i] = o;
        g_cur[i] = o;
    }
    if (i == 0) g_off[NN] = EE;
}
__global__ void k_fill(const int* __restrict__ src, const int* __restrict__ dst) {
    int e = blockIdx.x * 256 + threadIdx.x;
    if (e >= EE) return;
    int p = atomicAdd(&g_cur[dst[e]], 1);
    g_esrc[p] = src[e];
}

// ---------------- W split (hi/lo tf32) -------------------------------------
__global__ void k_wsplit(const float* __restrict__ W1, const float* __restrict__ W2) {
    int i = blockIdx.x * 256 + threadIdx.x;
    if (i >= 2 * 128 * 128) return;
    int which = i >> 14, j = i & 16383;
    float v = (which == 0 ? W1 : W2)[j];
    unsigned h = to_tf32(v);
    float lo_f = v - __uint_as_float(h);
    g_Whi[which][j] = h;
    g_Wlo[which][j] = to_tf32(lo_f);
}

// ---------------- tensor-core projection GEMM (3xTF32) ---------------------
// 64 rows x 128 cols per block, 4 warps (warp = 16 rows x 128 cols).
// Fused epilogue: write g_h + el/er attention dots per head.
__global__ void __launch_bounds__(128) k_gemm_tc(
    const float* __restrict__ xext, int use_internal, int widx,
    const float* __restrict__ al, const float* __restrict__ ar)
{
    const float* x = use_internal ? g_feat2 : xext;
    const unsigned* Wh = g_Whi[widx];
    const unsigned* Wl = g_Wlo[widx];

    __shared__ float    Xs[64][36];       // 64 rows x 32 k (+4 pad)
    __shared__ unsigned Whs[32][136];     // 32 k x 128 n (+8 pad)
    __shared__ unsigned Wls[32][136];

    int t = threadIdx.x;
    int lane = t & 31, w = t >> 5;
    int row0 = blockIdx.x * 64;
    int wr = w * 16;                       // warp row base within block
    int gq = lane >> 2, qc = lane & 3;     // group (0..7), tid-in-group (0..3)

    float acc[16][4];
#pragma unroll
    for (int nt = 0; nt < 16; nt++)
#pragma unroll
        for (int j = 0; j < 4; j++) acc[nt][j] = 0.f;

    for (int k0 = 0; k0 < 128; k0 += 32) {
        __syncthreads();
        // W chunk: 32 k x 128 n as uint4 (1024 uint4, 8/thread), hi + lo
#pragma unroll
        for (int l = 0; l < 8; l++) {
            int idx = t + l * 128;
            int kk = idx >> 5, c4 = idx & 31;
            *(uint4*)&Whs[kk][c4 * 4] = ((const uint4*)(Wh + (k0 + kk) * 128))[c4];
            *(uint4*)&Wls[kk][c4 * 4] = ((const uint4*)(Wl + (k0 + kk) * 128))[c4];
        }
        // X chunk: 64 rows x 32 k (float4 gmem loads, scalar smem stores)
#pragma unroll
        for (int l = 0; l < 4; l++) {
            int idx = t + l * 128;
            int r = idx >> 3, c4 = idx & 7;
            int n = row0 + r;
            float4 v = (n < NN) ? ((const float4*)(x + n * 128 + k0))[c4]
                                : make_float4(0.f, 0.f, 0.f, 0.f);
            Xs[r][c4 * 4 + 0] = v.x; Xs[r][c4 * 4 + 1] = v.y;
            Xs[r][c4 * 4 + 2] = v.z; Xs[r][c4 * 4 + 3] = v.w;
        }
        __syncthreads();

#pragma unroll
        for (int ks = 0; ks < 4; ks++) {
            int kb = ks * 8;
            float a0f = Xs[wr + gq][kb + qc];
            float a1f = Xs[wr + gq + 8][kb + qc];
            float a2f = Xs[wr + gq][kb + qc + 4];
            float a3f = Xs[wr + gq + 8][kb + qc + 4];
            unsigned ah0 = to_tf32(a0f), ah1 = to_tf32(a1f);
            unsigned ah2 = to_tf32(a2f), ah3 = to_tf32(a3f);
            unsigned al0 = to_tf32(a0f - __uint_as_float(ah0));
            unsigned al1_ = to_tf32(a1f - __uint_as_float(ah1));
            unsigned al2_ = to_tf32(a2f - __uint_as_float(ah2));
            unsigned al3_ = to_tf32(a3f - __uint_as_float(ah3));
#pragma unroll
            for (int nt = 0; nt < 16; nt++) {
                int nb = nt * 8 + gq;
                unsigned b0h = Whs[kb + qc][nb];
                unsigned b1h = Whs[kb + qc + 4][nb];
                unsigned b0l = Wls[kb + qc][nb];
                unsigned b1l = Wls[kb + qc + 4][nb];
                MMA_TF32(acc[nt], ah0, ah1, ah2, ah3, b0h, b1h);  // hi*hi
                MMA_TF32(acc[nt], ah0, ah1, ah2, ah3, b0l, b1l);  // hi*lo
                MMA_TF32(acc[nt], al0, al1_, al2_, al3_, b0h, b1h); // lo*hi
            }
        }
    }

    // ---- epilogue: store h, compute el/er ----
    int n0 = row0 + wr + gq;
    int n1 = n0 + 8;
    float pel0[4], per0[4], pel1[4], per1[4];
#pragma unroll
    for (int hd = 0; hd < 4; hd++) { pel0[hd] = per0[hd] = pel1[hd] = per1[hd] = 0.f; }

#pragma unroll
    for (int nt = 0; nt < 16; nt++) {
        int col = nt * 8 + 2 * qc;
        float a0 = al[col], a1 = al[col + 1];
        float r0 = ar[col], r1 = ar[col + 1];
        int hd = nt >> 2;
        pel0[hd] += acc[nt][0] * a0 + acc[nt][1] * a1;
        per0[hd] += acc[nt][0] * r0 + acc[nt][1] * r1;
        pel1[hd] += acc[nt][2] * a0 + acc[nt][3] * a1;
        per1[hd] += acc[nt][2] * r0 + acc[nt][3] * r1;
        if (n0 < NN) *(float2*)(g_h + n0 * 128 + col) = make_float2(acc[nt][0], acc[nt][1]);
        if (n1 < NN) *(float2*)(g_h + n1 * 128 + col) = make_float2(acc[nt][2], acc[nt][3]);
    }
    // reduce over the 4 lanes of each quad (lane bits 0,1)
#pragma unroll
    for (int hd = 0; hd < 4; hd++) {
#pragma unroll
        for (int o = 1; o <= 2; o <<= 1) {
            pel0[hd] += __shfl_xor_sync(0xffffffffu, pel0[hd], o);
            per0[hd] += __shfl_xor_sync(0xffffffffu, per0[hd], o);
            pel1[hd] += __shfl_xor_sync(0xffffffffu, pel1[hd], o);
            per1[hd] += __shfl_xor_sync(0xffffffffu, per1[hd], o);
        }
    }
    if (qc == 0) {
#pragma unroll
        for (int hd = 0; hd < 4; hd++) {
            if (n0 < NN) { g_el[n0 * 4 + hd] = pel0[hd]; g_er[n0 * 4 + hd] = per0[hd]; }
            if (n1 < NN) { g_el[n1 * 4 + hd] = pel1[hd]; g_er[n1 * 4 + hd] = per1[hd]; }
        }
    }
}

// ---------------- fused per-node softmax + aggregation ----------------------
__global__ void __launch_bounds__(256) k_node(
    const float* __restrict__ b, float* __restrict__ out, int layer)
{
    int gt = blockIdx.x * 256 + threadIdx.x;
    int n = gt >> 5;
    if (n >= NN) return;
    int lane = gt & 31;

    int off = g_off[n];
    int deg = g_off[n + 1] - off;

    float4 er4 = ((const float4*)g_er)[n];

    // pass 1: edge logits + warp max
    float4 m = make_float4(-1e30f, -1e30f, -1e30f, -1e30f);
    for (int j = lane; j < deg; j += 32) {
        int s = g_esrc[off + j];
        float4 l4 = ((const float4*)g_el)[s];
        float4 e4;
        e4.x = lrelu(l4.x + er4.x); e4.y = lrelu(l4.y + er4.y);
        e4.z = lrelu(l4.z + er4.z); e4.w = lrelu(l4.w + er4.w);
        ((float4*)g_e)[off + j] = e4;
        m.x = fmaxf(m.x, e4.x); m.y = fmaxf(m.y, e4.y);
        m.z = fmaxf(m.z, e4.z); m.w = fmaxf(m.w, e4.w);
    }
#pragma unroll
    for (int o = 16; o; o >>= 1) {
        m.x = fmaxf(m.x, __shfl_xor_sync(0xffffffffu, m.x, o));
        m.y = fmaxf(m.y, __shfl_xor_sync(0xffffffffu, m.y, o));
        m.z = fmaxf(m.z, __shfl_xor_sync(0xffffffffu, m.z, o));
        m.w = fmaxf(m.w, __shfl_xor_sync(0xffffffffu, m.w, o));
    }

    // pass 2: exp + warp sum
    float4 s4 = make_float4(0.f, 0.f, 0.f, 0.f);
    for (int j = lane; j < deg; j += 32) {
        float4 e4 = ((const float4*)g_e)[off + j];
        float4 ex;
        ex.x = __expf(e4.x - m.x); ex.y = __expf(e4.y - m.y);
        ex.z = __expf(e4.z - m.z); ex.w = __expf(e4.w - m.w);
        ((float4*)g_e)[off + j] = ex;
        s4.x += ex.x; s4.y += ex.y; s4.z += ex.z; s4.w += ex.w;
    }
#pragma unroll
    for (int o = 16; o; o >>= 1) {
        s4.x += __shfl_xor_sync(0xffffffffu, s4.x, o);
        s4.y += __shfl_xor_sync(0xffffffffu, s4.y, o);
        s4.z += __shfl_xor_sync(0xffffffffu, s4.z, o);
        s4.w += __shfl_xor_sync(0xffffffffu, s4.w, o);
    }
    int hd = lane >> 3;
    float rinv = 0.f;
    if (deg > 0) {
        float sh = hd == 0 ? s4.x : hd == 1 ? s4.y : hd == 2 ? s4.z : s4.w;
        rinv = 1.f / sh;
    }

    // pass 3: gather-aggregate
    float4 acc = make_float4(0.f, 0.f, 0.f, 0.f);
    const float4* hb = (const float4*)g_h;
    const float* ge = g_e;
    for (int j = 0; j < deg; j++) {
        int s = g_esrc[off + j];
        float a = ge[(off + j) * 4 + hd] * rinv;
        float4 hv = hb[s * 32 + lane];
        acc.x += hv.x * a; acc.y += hv.y * a;
        acc.z += hv.z * a; acc.w += hv.w * a;
    }

    float4 b4 = ((const float4*)b)[lane];
    acc.x += b4.x; acc.y += b4.y; acc.z += b4.z; acc.w += b4.w;

    if (layer == 1) {
        acc.x = fmaxf(acc.x, 0.f); acc.y = fmaxf(acc.y, 0.f);
        acc.z = fmaxf(acc.z, 0.f); acc.w = fmaxf(acc.w, 0.f);
        ((float4*)(g_feat2 + n * 128))[lane] = acc;
    } else {
#pragma unroll
        for (int o = 8; o <= 16; o <<= 1) {
            acc.x += __shfl_xor_sync(0xffffffffu, acc.x, o);
            acc.y += __shfl_xor_sync(0xffffffffu, acc.y, o);
            acc.z += __shfl_xor_sync(0xffffffffu, acc.z, o);
            acc.w += __shfl_xor_sync(0xffffffffu, acc.w, o);
        }
        if (lane < 8) {
            float4 r = make_float4(acc.x * 0.25f, acc.y * 0.25f,
                                   acc.z * 0.25f, acc.w * 0.25f);
            ((float4*)(out + n * 32))[lane] = r;
        }
    }
}

// ---------------- launch ---------------------------------------------------
extern "C" void kernel_launch(void* const* d_in, const int* in_sizes, int n_in,
                              void* d_out, int out_size)
{
    const float* feat = (const float*)d_in[0];
    const int*   src  = (const int*)d_in[1];
    const int*   dst  = (const int*)d_in[2];
    const float* W1   = (const float*)d_in[3];
    const float* al1  = (const float*)d_in[4];
    const float* ar1  = (const float*)d_in[5];
    const float* b1   = (const float*)d_in[6];
    const float* W2   = (const float*)d_in[7];
    const float* al2  = (const float*)d_in[8];
    const float* ar2  = (const float*)d_in[9];
    const float* b2   = (const float*)d_in[10];
    float* out = (float*)d_out;

    const int G_N    = (NN + 255) / 256;
    const int G_E    = (EE + 255) / 256;
    const int G_GEMM = (NN + 63) / 64;
    const int G_NODE = (NN * 32 + 255) / 256;

    // ---- W split + CSR build ----
    k_wsplit<<<(2 * 128 * 128 + 255) / 256, 256>>>(W1, W2);
    k_zero_cnt<<<G_N, 256>>>();
    k_count<<<G_E, 256>>>(dst);
    k_scan1<<<NB, 1024>>>();
    k_scan2<<<1, 128>>>();
    k_scan3<<<G_N, 256>>>();
    k_fill<<<G_E, 256>>>(src, dst);

    // ---- layer 1 ----
    k_gemm_tc<<<G_GEMM, 128>>>(feat, 0, 0, al1, ar1);
    k_node<<<G_NODE, 256>>>(b1, nullptr, 1);

    // ---- layer 2 ----
    k_gemm_tc<<<G_GEMM, 128>>>(nullptr, 1, 1, al2, ar2);
    k_node<<<G_NODE, 256>>>(b2, out, 2);
}

// round 5
// speedup vs baseline: 2.4378x; 1.1964x over previous
#include <cuda_runtime.h>

#define NN 100000
#define EE 800000
#define NB 98            // scan blocks: ceil(100000/1024)

// ---------------- scratch (device globals) ---------------------------------
__device__ float    g_h[NN * 128];      // projected features
__device__ float    g_feat2[NN * 128];  // relu(out1 + b1) -> layer-2 input
__device__ float    g_el[NN * 4];
__device__ float    g_er[NN * 4];
__device__ float    g_e[EE * 4];        // exp(e - m), CSR order
__device__ int      g_cnt[NN];
__device__ int      g_off[NN + 1];      // CSR row offsets (by dst)
__device__ int      g_cur[NN];          // fill cursors
__device__ int      g_esrc[EE];         // src node per CSR slot
__device__ int      g_bsum[NB];
// W as packed bf16 pairs (k, k+1) along K: [layer][ (k/2)*128 + n ]
__device__ unsigned g_Whi[2][64 * 128];
__device__ unsigned g_Wlo[2][64 * 128];

__device__ __forceinline__ float lrelu(float v) { return v > 0.f ? v : 0.2f * v; }

// split two fp32 into packed bf16 hi pair + bf16 lo (residual) pair.
// pair low half = x0 (even k), high half = x1 (odd k).
__device__ __forceinline__ void split_pair(float x0, float x1,
                                           unsigned& hi, unsigned& lo) {
    unsigned hp;
    asm("cvt.rn.bf16x2.f32 %0, %1, %2;" : "=r"(hp) : "f"(x1), "f"(x0));
    float f0 = __uint_as_float(hp << 16);          // bf16->f32 exact
    float f1 = __uint_as_float(hp & 0xffff0000u);
    unsigned lp;
    asm("cvt.rn.bf16x2.f32 %0, %1, %2;" : "=r"(lp) : "f"(x1 - f1), "f"(x0 - f0));
    hi = hp; lo = lp;
}

#define MMA_BF16(c, a0, a1, a2, a3, b0, b1)                                    \
    asm volatile(                                                              \
        "mma.sync.aligned.m16n8k16.row.col.f32.bf16.bf16.f32 "                 \
        "{%0,%1,%2,%3}, {%4,%5,%6,%7}, {%8,%9}, {%0,%1,%2,%3};"                \
        : "+f"(c[0]), "+f"(c[1]), "+f"(c[2]), "+f"(c[3])                       \
        : "r"(a0), "r"(a1), "r"(a2), "r"(a3), "r"(b0), "r"(b1))

// ---------------- prep: W split + zero counters -----------------------------
__global__ void k_prep(const float* __restrict__ W1, const float* __restrict__ W2) {
    int i = blockIdx.x * 256 + threadIdx.x;
    if (i < 2 * 64 * 128) {
        int which = i >> 13, j = i & 8191;
        int kp = j >> 7, n = j & 127;
        const float* W = which == 0 ? W1 : W2;
        float x0 = W[(2 * kp) * 128 + n];
        float x1 = W[(2 * kp + 1) * 128 + n];
        unsigned hi, lo;
        split_pair(x0, x1, hi, lo);
        g_Whi[which][kp * 128 + n] = hi;
        g_Wlo[which][kp * 128 + n] = lo;
    }
    if (i < NN) g_cnt[i] = 0;
}

// ---------------- CSR build ------------------------------------------------
__global__ void k_count(const int* __restrict__ dst) {
    int e = blockIdx.x * 256 + threadIdx.x;
    if (e < EE) atomicAdd(&g_cnt[dst[e]], 1);
}
__global__ void __launch_bounds__(1024) k_scan1() {
    __shared__ int sh[1024];
    int t = threadIdx.x, i = blockIdx.x * 1024 + t;
    int v = (i < NN) ? g_cnt[i] : 0;
    sh[t] = v; __syncthreads();
#pragma unroll
    for (int d = 1; d < 1024; d <<= 1) {
        int add = (t >= d) ? sh[t - d] : 0;
        __syncthreads();
        sh[t] += add;
        __syncthreads();
    }
    if (i < NN) g_off[i] = sh[t] - v;
    if (t == 1023) g_bsum[blockIdx.x] = sh[1023];
}
__global__ void __launch_bounds__(128) k_scan2() {
    __shared__ int sh[128];
    int t = threadIdx.x;
    int v = (t < NB) ? g_bsum[t] : 0;
    sh[t] = v; __syncthreads();
#pragma unroll
    for (int d = 1; d < 128; d <<= 1) {
        int add = (t >= d) ? sh[t - d] : 0;
        __syncthreads();
        sh[t] += add;
        __syncthreads();
    }
    if (t < NB) g_bsum[t] = sh[t] - v;   // exclusive
}
__global__ void k_scan3() {
    int i = blockIdx.x * 256 + threadIdx.x;
    if (i < NN) {
        int o = g_off[i] + g_bsum[i >> 10];
        g_off[i] = o;
        g_cur[i] = o;
    }
    if (i == 0) g_off[NN] = EE;
}
__global__ void k_fill(const int* __restrict__ src, const int* __restrict__ dst) {
    int e = blockIdx.x * 256 + threadIdx.x;
    if (e >= EE) return;
    int p = atomicAdd(&g_cur[dst[e]], 1);
    g_esrc[p] = src[e];
}

// ---------------- tensor-core projection GEMM (3xBF16 split) ----------------
// 64 rows x 128 cols per block, 4 warps (warp = 16 rows x 128 cols).
// K chunks of 32 (= 2 mma K-steps of 16). Fused el/er epilogue.
__global__ void __launch_bounds__(128) k_gemm_tc(
    const float* __restrict__ xext, int use_internal, int widx,
    const float* __restrict__ al, const float* __restrict__ ar)
{
    const float* x = use_internal ? g_feat2 : xext;
    const unsigned* Wh = g_Whi[widx];
    const unsigned* Wl = g_Wlo[widx];

    __shared__ unsigned Whs[16][136];   // 16 kpairs x 128 n (+8 pad)
    __shared__ unsigned Wls[16][136];
    __shared__ unsigned Xh[64][20];     // 64 rows x 16 kpairs (+4 pad)
    __shared__ unsigned Xl[64][20];

    int t = threadIdx.x;
    int lane = t & 31, w = t >> 5;
    int row0 = blockIdx.x * 64;
    int wr = w * 16;
    int gq = lane >> 2, qc = lane & 3;

    float acc[16][4];
#pragma unroll
    for (int nt = 0; nt < 16; nt++)
#pragma unroll
        for (int j = 0; j < 4; j++) acc[nt][j] = 0.f;

    for (int k0 = 0; k0 < 128; k0 += 32) {
        int kp0 = k0 >> 1;   // base kpair
        __syncthreads();
        // W chunk: 16 kpairs x 128 n (hi + lo), uint4 loads
#pragma unroll
        for (int l = 0; l < 4; l++) {
            int idx = t + l * 128;
            int kk = idx >> 5, c4 = idx & 31;
            *(uint4*)&Whs[kk][c4 * 4] = ((const uint4*)(Wh + (kp0 + kk) * 128))[c4];
            *(uint4*)&Wls[kk][c4 * 4] = ((const uint4*)(Wl + (kp0 + kk) * 128))[c4];
        }
        // X chunk: 64 rows x 32 k fp32, split+pack to bf16 pairs
#pragma unroll
        for (int l = 0; l < 4; l++) {
            int idx = t + l * 128;
            int r = idx >> 3, c4 = idx & 7;
            int n = row0 + r;
            float4 v = (n < NN) ? ((const float4*)(x + n * 128 + k0))[c4]
                                : make_float4(0.f, 0.f, 0.f, 0.f);
            unsigned h0, l0, h1, l1;
            split_pair(v.x, v.y, h0, l0);
            split_pair(v.z, v.w, h1, l1);
            Xh[r][c4 * 2] = h0; Xh[r][c4 * 2 + 1] = h1;
            Xl[r][c4 * 2] = l0; Xl[r][c4 * 2 + 1] = l1;
        }
        __syncthreads();

#pragma unroll
        for (int ks = 0; ks < 2; ks++) {
            int kb = ks * 8;
            unsigned ah0 = Xh[wr + gq][kb + qc];
            unsigned ah1 = Xh[wr + gq + 8][kb + qc];
            unsigned ah2 = Xh[wr + gq][kb + qc + 4];
            unsigned ah3 = Xh[wr + gq + 8][kb + qc + 4];
            unsigned al0 = Xl[wr + gq][kb + qc];
            unsigned al1 = Xl[wr + gq + 8][kb + qc];
            unsigned al2 = Xl[wr + gq][kb + qc + 4];
            unsigned al3 = Xl[wr + gq + 8][kb + qc + 4];
#pragma unroll
            for (int nt = 0; nt < 16; nt++) {
                int nb = nt * 8 + gq;
                unsigned b0h = Whs[kb + qc][nb];
                unsigned b1h = Whs[kb + qc + 4][nb];
                unsigned b0l = Wls[kb + qc][nb];
                unsigned b1l = Wls[kb + qc + 4][nb];
                MMA_BF16(acc[nt], ah0, ah1, ah2, ah3, b0h, b1h);  // hi*hi
                MMA_BF16(acc[nt], ah0, ah1, ah2, ah3, b0l, b1l);  // hi*lo
                MMA_BF16(acc[nt], al0, al1, al2, al3, b0h, b1h);  // lo*hi
            }
        }
    }

    // ---- epilogue: store h, compute el/er ----
    int n0 = row0 + wr + gq;
    int n1 = n0 + 8;
    float pel0[4], per0[4], pel1[4], per1[4];
#pragma unroll
    for (int hd = 0; hd < 4; hd++) { pel0[hd] = per0[hd] = pel1[hd] = per1[hd] = 0.f; }

#pragma unroll
    for (int nt = 0; nt < 16; nt++) {
        int col = nt * 8 + 2 * qc;
        float a0 = al[col], a1 = al[col + 1];
        float r0 = ar[col], r1 = ar[col + 1];
        int hd = nt >> 2;
        pel0[hd] += acc[nt][0] * a0 + acc[nt][1] * a1;
        per0[hd] += acc[nt][0] * r0 + acc[nt][1] * r1;
        pel1[hd] += acc[nt][2] * a0 + acc[nt][3] * a1;
        per1[hd] += acc[nt][2] * r0 + acc[nt][3] * r1;
        if (n0 < NN) *(float2*)(g_h + n0 * 128 + col) = make_float2(acc[nt][0], acc[nt][1]);
        if (n1 < NN) *(float2*)(g_h + n1 * 128 + col) = make_float2(acc[nt][2], acc[nt][3]);
    }
#pragma unroll
    for (int hd = 0; hd < 4; hd++) {
#pragma unroll
        for (int o = 1; o <= 2; o <<= 1) {
            pel0[hd] += __shfl_xor_sync(0xffffffffu, pel0[hd], o);
            per0[hd] += __shfl_xor_sync(0xffffffffu, per0[hd], o);
            pel1[hd] += __shfl_xor_sync(0xffffffffu, pel1[hd], o);
            per1[hd] += __shfl_xor_sync(0xffffffffu, per1[hd], o);
        }
    }
    if (qc == 0) {
#pragma unroll
        for (int hd = 0; hd < 4; hd++) {
            if (n0 < NN) { g_el[n0 * 4 + hd] = pel0[hd]; g_er[n0 * 4 + hd] = per0[hd]; }
            if (n1 < NN) { g_el[n1 * 4 + hd] = pel1[hd]; g_er[n1 * 4 + hd] = per1[hd]; }
        }
    }
}

// ---------------- fused per-node softmax + aggregation ----------------------
__global__ void __launch_bounds__(256) k_node(
    const float* __restrict__ b, float* __restrict__ out, int layer)
{
    int gt = blockIdx.x * 256 + threadIdx.x;
    int n = gt >> 5;
    if (n >= NN) return;
    int lane = gt & 31;

    int off = g_off[n];
    int deg = g_off[n + 1] - off;

    float4 er4 = ((const float4*)g_er)[n];

    // pass 1: logits + warp max (no store; recomputed in pass 2)
    float4 m = make_float4(-1e30f, -1e30f, -1e30f, -1e30f);
    for (int j = lane; j < deg; j += 32) {
        int s = g_esrc[off + j];
        float4 l4 = ((const float4*)g_el)[s];
        m.x = fmaxf(m.x, lrelu(l4.x + er4.x));
        m.y = fmaxf(m.y, lrelu(l4.y + er4.y));
        m.z = fmaxf(m.z, lrelu(l4.z + er4.z));
        m.w = fmaxf(m.w, lrelu(l4.w + er4.w));
    }
#pragma unroll
    for (int o = 16; o; o >>= 1) {
        m.x = fmaxf(m.x, __shfl_xor_sync(0xffffffffu, m.x, o));
        m.y = fmaxf(m.y, __shfl_xor_sync(0xffffffffu, m.y, o));
        m.z = fmaxf(m.z, __shfl_xor_sync(0xffffffffu, m.z, o));
        m.w = fmaxf(m.w, __shfl_xor_sync(0xffffffffu, m.w, o));
    }

    // pass 2: recompute logits, exp, store exp, warp sum
    float4 s4 = make_float4(0.f, 0.f, 0.f, 0.f);
    for (int j = lane; j < deg; j += 32) {
        int s = g_esrc[off + j];
        float4 l4 = ((const float4*)g_el)[s];
        float4 ex;
        ex.x = __expf(lrelu(l4.x + er4.x) - m.x);
        ex.y = __expf(lrelu(l4.y + er4.y) - m.y);
        ex.z = __expf(lrelu(l4.z + er4.z) - m.z);
        ex.w = __expf(lrelu(l4.w + er4.w) - m.w);
        ((float4*)g_e)[off + j] = ex;
        s4.x += ex.x; s4.y += ex.y; s4.z += ex.z; s4.w += ex.w;
    }
#pragma unroll
    for (int o = 16; o; o >>= 1) {
        s4.x += __shfl_xor_sync(0xffffffffu, s4.x, o);
        s4.y += __shfl_xor_sync(0xffffffffu, s4.y, o);
        s4.z += __shfl_xor_sync(0xffffffffu, s4.z, o);
        s4.w += __shfl_xor_sync(0xffffffffu, s4.w, o);
    }
    int hd = lane >> 3;
    float rinv = 0.f;
    if (deg > 0) {
        float sh = hd == 0 ? s4.x : hd == 1 ? s4.y : hd == 2 ? s4.z : s4.w;
        rinv = 1.f / sh;
    }

    // pass 3: gather-aggregate, 4-wide unrolled for MLP (rinv factored out)
    float4 acc = make_float4(0.f, 0.f, 0.f, 0.f);
    const float4* hb = (const float4*)g_h;
    const float* ge = g_e;
    int j = 0;
    for (; j + 4 <= deg; j += 4) {
        int p = off + j;
        int s0 = g_esrc[p], s1 = g_esrc[p + 1], s2 = g_esrc[p + 2], s3 = g_esrc[p + 3];
        float a0 = ge[p * 4 + hd],       a1 = ge[(p + 1) * 4 + hd];
        float a2 = ge[(p + 2) * 4 + hd], a3 = ge[(p + 3) * 4 + hd];
        float4 h0 = hb[s0 * 32 + lane], h1 = hb[s1 * 32 + lane];
        float4 h2 = hb[s2 * 32 + lane], h3 = hb[s3 * 32 + lane];
        acc.x += (h0.x * a0 + h1.x * a1) + (h2.x * a2 + h3.x * a3);
        acc.y += (h0.y * a0 + h1.y * a1) + (h2.y * a2 + h3.y * a3);
        acc.z += (h0.z * a0 + h1.z * a1) + (h2.z * a2 + h3.z * a3);
        acc.w += (h0.w * a0 + h1.w * a1) + (h2.w * a2 + h3.w * a3);
    }
    for (; j < deg; j++) {
        int p = off + j;
        int s = g_esrc[p];
        float a = ge[p * 4 + hd];
        float4 hv = hb[s * 32 + lane];
        acc.x += hv.x * a; acc.y += hv.y * a;
        acc.z += hv.z * a; acc.w += hv.w * a;
    }
    acc.x *= rinv; acc.y *= rinv; acc.z *= rinv; acc.w *= rinv;

    float4 b4 = ((const float4*)b)[lane];
    acc.x += b4.x; acc.y += b4.y; acc.z += b4.z; acc.w += b4.w;

    if (layer == 1) {
        acc.x = fmaxf(acc.x, 0.f); acc.y = fmaxf(acc.y, 0.f);
        acc.z = fmaxf(acc.z, 0.f); acc.w = fmaxf(acc.w, 0.f);
        ((float4*)(g_feat2 + n * 128))[lane] = acc;
    } else {
#pragma unroll
        for (int o = 8; o <= 16; o <<= 1) {
            acc.x += __shfl_xor_sync(0xffffffffu, acc.x, o);
            acc.y += __shfl_xor_sync(0xffffffffu, acc.y, o);
            acc.z += __shfl_xor_sync(0xffffffffu, acc.z, o);
            acc.w += __shfl_xor_sync(0xffffffffu, acc.w, o);
        }
        if (lane < 8) {
            float4 r = make_float4(acc.x * 0.25f, acc.y * 0.25f,
                                   acc.z * 0.25f, acc.w * 0.25f);
            ((float4*)(out + n * 32))[lane] = r;
        }
    }
}

// ---------------- launch ---------------------------------------------------
extern "C" void kernel_launch(void* const* d_in, const int* in_sizes, int n_in,
                              void* d_out, int out_size)
{
    const float* feat = (const float*)d_in[0];
    const int*   src  = (const int*)d_in[1];
    const int*   dst  = (const int*)d_in[2];
    const float* W1   = (const float*)d_in[3];
    const float* al1  = (const float*)d_in[4];
    const float* ar1  = (const float*)d_in[5];
    const float* b1   = (const float*)d_in[6];
    const float* W2   = (const float*)d_in[7];
    const float* al2  = (const float*)d_in[8];
    const float* ar2  = (const float*)d_in[9];
    const float* b2   = (const float*)d_in[10];
    float* out = (float*)d_out;

    const int G_PREP = (NN + 255) / 256;   // covers both wsplit (32k) and zero (100k)
    const int G_N    = (NN + 255) / 256;
    const int G_E    = (EE + 255) / 256;
    const int G_GEMM = (NN + 63) / 64;
    const int G_NODE = (NN * 32 + 255) / 256;

    // launch order arranged so ncu (-s 5 -c 1) profiles the layer-1 GEMM
    k_prep<<<G_PREP, 256>>>(W1, W2);            // 0
    k_count<<<G_E, 256>>>(dst);                 // 1
    k_scan1<<<NB, 1024>>>();                    // 2
    k_scan2<<<1, 128>>>();                      // 3
    k_scan3<<<G_N, 256>>>();                    // 4
    k_gemm_tc<<<G_GEMM, 128>>>(feat, 0, 0, al1, ar1);   // 5  <- profiled
    k_fill<<<G_E, 256>>>(src, dst);             // 6
    k_node<<<G_NODE, 256>>>(b1, nullptr, 1);    // 7
    k_gemm_tc<<<G_GEMM, 128>>>(nullptr, 1, 1, al2, ar2); // 8
    k_node<<<G_NODE, 256>>>(b2, out, 2);        // 9
}